// round 1
// baseline (speedup 1.0000x reference)
#include <cuda_runtime.h>
#include <math.h>

// Problem constants
// B=4, S=1024, D=1024, H=16, DH=64
// qkv scratch layout: [which(6)][b(4)][h(16)][s(1024)][d(64)]
__device__ float g_qkv[6ull * 4 * 16 * 1024 * 64];

struct WPack {
    const float* W[6];
    const float* b[6];
};

// ---------------------------------------------------------------------------
// Fused 6-way projection GEMM: X[4096,1024] @ W_i[1024,1024] + b_i
// Block tile 128x128, BK=8, 256 threads, 8x8 per-thread microtile.
// Writes directly into head-major scratch layout.
// ---------------------------------------------------------------------------
__global__ __launch_bounds__(256) void qkv_gemm_kernel(const float* __restrict__ X, WPack wp)
{
    __shared__ float As[8][128];   // transposed A tile
    __shared__ float Bs[8][128];

    const int tid = threadIdx.x;
    const int bn  = blockIdx.x;    // 0..47 over N=6144
    const int bm  = blockIdx.y;    // 0..31 over M=4096

    const int which = (bn * 128) >> 10;     // which of 6 weights
    const int nbase = (bn * 128) & 1023;    // column base within that weight

    const float* __restrict__ W    = wp.W[which];
    const float* __restrict__ bias = wp.b[which];

    const int tx = tid & 15;
    const int ty = tid >> 4;

    // load mappings
    const int a_m = tid >> 1;               // 0..127
    const int a_k = (tid & 1) << 2;         // 0 or 4
    const int b_k = tid >> 5;               // 0..7
    const int b_n = (tid & 31) << 2;        // 0..124

    const float* Aptr = X + (size_t)(bm * 128 + a_m) * 1024 + a_k;
    const float* Bptr = W + (size_t)b_k * 1024 + nbase + b_n;

    float acc[8][8];
#pragma unroll
    for (int i = 0; i < 8; i++)
#pragma unroll
        for (int j = 0; j < 8; j++) acc[i][j] = 0.f;

    for (int k0 = 0; k0 < 1024; k0 += 8) {
        float4 av = *reinterpret_cast<const float4*>(Aptr + k0);
        float4 bv = *reinterpret_cast<const float4*>(Bptr + (size_t)k0 * 1024);

        As[a_k + 0][a_m] = av.x;
        As[a_k + 1][a_m] = av.y;
        As[a_k + 2][a_m] = av.z;
        As[a_k + 3][a_m] = av.w;
        *reinterpret_cast<float4*>(&Bs[b_k][b_n]) = bv;
        __syncthreads();

#pragma unroll
        for (int kk = 0; kk < 8; kk++) {
            float4 a0 = *reinterpret_cast<const float4*>(&As[kk][ty << 2]);
            float4 a1 = *reinterpret_cast<const float4*>(&As[kk][64 + (ty << 2)]);
            float4 b0 = *reinterpret_cast<const float4*>(&Bs[kk][tx << 2]);
            float4 b1 = *reinterpret_cast<const float4*>(&Bs[kk][64 + (tx << 2)]);
            float a[8] = {a0.x, a0.y, a0.z, a0.w, a1.x, a1.y, a1.z, a1.w};
            float b[8] = {b0.x, b0.y, b0.z, b0.w, b1.x, b1.y, b1.z, b1.w};
#pragma unroll
            for (int i = 0; i < 8; i++)
#pragma unroll
                for (int j = 0; j < 8; j++)
                    acc[i][j] = fmaf(a[i], b[j], acc[i][j]);
        }
        __syncthreads();
    }

    // epilogue: bias add + scatter to [which][b][h][s][d]
#pragma unroll
    for (int i = 0; i < 8; i++) {
        int mrow = bm * 128 + ((i < 4) ? (ty << 2) + i : 64 + (ty << 2) + (i - 4));
        int bb = mrow >> 10;
        int s  = mrow & 1023;
#pragma unroll
        for (int j = 0; j < 8; j++) {
            int n = nbase + ((j < 4) ? (tx << 2) + j : 64 + (tx << 2) + (j - 4));
            int h = n >> 6;
            int d = n & 63;
            g_qkv[(((size_t)which * 4 + bb) * 16 + h) * 65536 + (size_t)s * 64 + d]
                = acc[i][j] + bias[n];
        }
    }
}

// ---------------------------------------------------------------------------
// Fused flash-attention (fp32, online softmax).
// One block: one (qtile of 64 rows) x (b,h) for a given attention stream.
// type=0 writes w0*ctx to out; type=1 (launched after) accumulates w1*sctx.
// ---------------------------------------------------------------------------
__global__ __launch_bounds__(256) void attn_kernel(const float* __restrict__ attn_w,
                                                   float* __restrict__ out, int type)
{
    extern __shared__ float sm[];
    float (*Qs)[65] = reinterpret_cast<float(*)[65]>(sm);                 // Q tile (pre-scaled)
    float (*Ks)[65] = reinterpret_cast<float(*)[65]>(sm + 64 * 65);       // K tile
    float (*Ss)[65] = reinterpret_cast<float(*)[65]>(sm + 2 * 64 * 65);   // P tile
    float (*Vs)[68] = reinterpret_cast<float(*)[68]>(sm + 3 * 64 * 65);   // V tile (float4 rows)

    const int tid = threadIdx.x;
    const int tx = tid & 15;
    const int ty = tid >> 4;
    const int qt = blockIdx.x;    // 0..15
    const int bh = blockIdx.y;    // 0..63
    const int b = bh >> 4;
    const int h = bh & 15;

    const size_t headoff = ((size_t)b * 16 + h) * 65536;
    const float* qg = g_qkv + (size_t)(type * 3 + 0) * 4194304 + headoff;
    const float* kg = g_qkv + (size_t)(type * 3 + 1) * 4194304 + headoff;
    const float* vg = g_qkv + (size_t)(type * 3 + 2) * 4194304 + headoff;

    // Load Q tile once, folding in 1/sqrt(DH) = 0.125
#pragma unroll
    for (int p = 0; p < 4; p++) {
        int lin = p * 1024 + tid * 4;
        int r = lin >> 6, d = lin & 63;
        float4 v = *reinterpret_cast<const float4*>(qg + (size_t)qt * 4096 + lin);
        Qs[r][d + 0] = v.x * 0.125f;
        Qs[r][d + 1] = v.y * 0.125f;
        Qs[r][d + 2] = v.z * 0.125f;
        Qs[r][d + 3] = v.w * 0.125f;
    }

    float O[4][4];
    float M[4], L[4];
#pragma unroll
    for (int i = 0; i < 4; i++) {
        M[i] = -1e30f;
        L[i] = 0.f;
#pragma unroll
        for (int j = 0; j < 4; j++) O[i][j] = 0.f;
    }

    const int r0 = ty << 2;   // this thread's 4 query rows
    const int c0 = tx << 2;   // this thread's 4 key cols (and 4 d cols in PV)

    for (int kt = 0; kt < 16; kt++) {
        __syncthreads();   // previous iteration's readers of Ks/Vs/Ss are done
#pragma unroll
        for (int p = 0; p < 4; p++) {
            int lin = p * 1024 + tid * 4;
            int r = lin >> 6, d = lin & 63;
            float4 kv = *reinterpret_cast<const float4*>(kg + (size_t)kt * 4096 + lin);
            Ks[r][d + 0] = kv.x;
            Ks[r][d + 1] = kv.y;
            Ks[r][d + 2] = kv.z;
            Ks[r][d + 3] = kv.w;
            float4 vv = *reinterpret_cast<const float4*>(vg + (size_t)kt * 4096 + lin);
            *reinterpret_cast<float4*>(&Vs[r][d]) = vv;
        }
        __syncthreads();

        // S = Q K^T (scaled) for this 64x64 tile; 4x4 per thread
        float S[4][4];
#pragma unroll
        for (int i = 0; i < 4; i++)
#pragma unroll
            for (int j = 0; j < 4; j++) S[i][j] = 0.f;

#pragma unroll 8
        for (int dd = 0; dd < 64; dd++) {
            float a[4], bb[4];
#pragma unroll
            for (int i = 0; i < 4; i++) a[i] = Qs[r0 + i][dd];
#pragma unroll
            for (int j = 0; j < 4; j++) bb[j] = Ks[c0 + j][dd];
#pragma unroll
            for (int i = 0; i < 4; i++)
#pragma unroll
                for (int j = 0; j < 4; j++)
                    S[i][j] = fmaf(a[i], bb[j], S[i][j]);
        }

        // Online softmax update (row stats via shfl across the 16 tx lanes)
#pragma unroll
        for (int i = 0; i < 4; i++) {
            float tm = fmaxf(fmaxf(S[i][0], S[i][1]), fmaxf(S[i][2], S[i][3]));
#pragma unroll
            for (int m = 1; m < 16; m <<= 1)
                tm = fmaxf(tm, __shfl_xor_sync(0xffffffffu, tm, m));
            float newM = fmaxf(M[i], tm);
            float sc = __expf(M[i] - newM);
            float ts = 0.f;
#pragma unroll
            for (int j = 0; j < 4; j++) {
                float p = __expf(S[i][j] - newM);
                S[i][j] = p;
                ts += p;
            }
#pragma unroll
            for (int m = 1; m < 16; m <<= 1)
                ts += __shfl_xor_sync(0xffffffffu, ts, m);
            L[i] = L[i] * sc + ts;
            M[i] = newM;
#pragma unroll
            for (int j = 0; j < 4; j++) O[i][j] *= sc;
            Ss[r0 + i][c0 + 0] = S[i][0];
            Ss[r0 + i][c0 + 1] = S[i][1];
            Ss[r0 + i][c0 + 2] = S[i][2];
            Ss[r0 + i][c0 + 3] = S[i][3];
        }
        __syncthreads();

        // O += P V  (thread owns rows r0..r0+3, d-cols c0..c0+3)
#pragma unroll 8
        for (int c = 0; c < 64; c++) {
            float a[4];
#pragma unroll
            for (int i = 0; i < 4; i++) a[i] = Ss[r0 + i][c];
            float4 bv = *reinterpret_cast<const float4*>(&Vs[c][c0]);
            float bb[4] = {bv.x, bv.y, bv.z, bv.w};
#pragma unroll
            for (int i = 0; i < 4; i++)
#pragma unroll
                for (int j = 0; j < 4; j++)
                    O[i][j] = fmaf(a[i], bb[j], O[i][j]);
        }
    }

    // combine weight: softmax(attn_w)[type]
    float w0a = attn_w[0], w1a = attn_w[1];
    float mx = fmaxf(w0a, w1a);
    float e0 = __expf(w0a - mx), e1 = __expf(w1a - mx);
    float w = ((type == 0) ? e0 : e1) / (e0 + e1);

#pragma unroll
    for (int i = 0; i < 4; i++) {
        float inv = w / L[i];
        int s = qt * 64 + r0 + i;
        float* op = out + ((size_t)b * 1024 + s) * 1024 + h * 64 + c0;
#pragma unroll
        for (int j = 0; j < 4; j++) {
            float v = O[i][j] * inv;
            if (type == 0) op[j] = v;
            else           op[j] += v;
        }
    }
}

// ---------------------------------------------------------------------------
// Launch
// ---------------------------------------------------------------------------
extern "C" void kernel_launch(void* const* d_in, const int* in_sizes, int n_in,
                              void* d_out, int out_size)
{
    (void)in_sizes; (void)n_in; (void)out_size;
    const float* x = (const float*)d_in[0];
    WPack wp;
    for (int i = 0; i < 6; i++) {
        wp.W[i] = (const float*)d_in[1 + 2 * i];
        wp.b[i] = (const float*)d_in[2 + 2 * i];
    }
    const float* attn_w = (const float*)d_in[13];
    float* out = (float*)d_out;

    const int ATTN_SMEM = (3 * 64 * 65 + 64 * 68) * 4;  // 67328 bytes
    cudaFuncSetAttribute(attn_kernel, cudaFuncAttributeMaxDynamicSharedMemorySize, ATTN_SMEM);

    // 1) six projections fused into one GEMM over N=6144
    qkv_gemm_kernel<<<dim3(48, 32), 256>>>(x, wp);

    // 2) attention stream 0 writes w0*ctx, stream 1 accumulates w1*sctx
    attn_kernel<<<dim3(16, 64), 256, ATTN_SMEM>>>(attn_w, out, 0);
    attn_kernel<<<dim3(16, 64), 256, ATTN_SMEM>>>(attn_w, out, 1);
}

// round 5
// speedup vs baseline: 2.4351x; 2.4351x over previous
#include <cuda_runtime.h>
#include <cuda_bf16.h>
#include <cstdint>
#include <math.h>

// Problem constants: B=4, S=1024, D=1024, H=16, DH=64
// head-major scratch: [which(6)][b(4)][h(16)][s(1024)][d(64)], bf16 hi/lo split
__device__ __nv_bfloat16 g_qkv_hi[6ull * 4 * 16 * 1024 * 64];
__device__ __nv_bfloat16 g_qkv_lo[6ull * 4 * 16 * 1024 * 64];
// bf16 split GEMM operands
__device__ __nv_bfloat16 g_xhi[4096ull * 1024];
__device__ __nv_bfloat16 g_xlo[4096ull * 1024];
// W transposed to [which][n][k] so B tiles are K-major
__device__ __nv_bfloat16 g_wthi[6ull * 1024 * 1024];
__device__ __nv_bfloat16 g_wtlo[6ull * 1024 * 1024];

struct WPack {
    const float* W[6];
    const float* b[6];
};

// ---------------------------------------------------------------------------
// mma / ldmatrix helpers (sm_80+ portable — NO tcgen05, sm_100 target)
// ---------------------------------------------------------------------------
__device__ __forceinline__ uint32_t smem_u32(const void* p) {
    uint32_t a;
    asm("{ .reg .u64 t; cvta.to.shared.u64 t, %1; cvt.u32.u64 %0, t; }" : "=r"(a) : "l"(p));
    return a;
}

#define LDSM_X4(r0, r1, r2, r3, addr) \
    asm volatile("ldmatrix.sync.aligned.m8n8.x4.shared.b16 {%0,%1,%2,%3}, [%4];" \
                 : "=r"(r0), "=r"(r1), "=r"(r2), "=r"(r3) : "r"(addr))
#define LDSM_X4_T(r0, r1, r2, r3, addr) \
    asm volatile("ldmatrix.sync.aligned.m8n8.x4.trans.shared.b16 {%0,%1,%2,%3}, [%4];" \
                 : "=r"(r0), "=r"(r1), "=r"(r2), "=r"(r3) : "r"(addr))

#define MMA_BF16(d, a, b0_, b1_) \
    asm volatile("mma.sync.aligned.m16n8k16.row.col.f32.bf16.bf16.f32 " \
                 "{%0,%1,%2,%3}, {%4,%5,%6,%7}, {%8,%9}, {%0,%1,%2,%3};" \
                 : "+f"((d)[0]), "+f"((d)[1]), "+f"((d)[2]), "+f"((d)[3]) \
                 : "r"((a)[0]), "r"((a)[1]), "r"((a)[2]), "r"((a)[3]), "r"(b0_), "r"(b1_))

__device__ __forceinline__ uint32_t pack_bf16x2(float a, float b) {
    __nv_bfloat162 t = __floats2bfloat162_rn(a, b);
    return *reinterpret_cast<uint32_t*>(&t);
}

// ---------------------------------------------------------------------------
// Convert X -> bf16 hi/lo
// ---------------------------------------------------------------------------
__global__ __launch_bounds__(256) void convert_x_kernel(const float* __restrict__ x)
{
    int i = blockIdx.x * 256 + threadIdx.x;
    float v = x[i];
    __nv_bfloat16 hi = __float2bfloat16(v);
    __nv_bfloat16 lo = __float2bfloat16(v - __bfloat162float(hi));
    g_xhi[i] = hi;
    g_xlo[i] = lo;
}

// ---------------------------------------------------------------------------
// Convert + transpose W[k][n] -> Wt[n][k] bf16 hi/lo
// ---------------------------------------------------------------------------
__global__ __launch_bounds__(256) void convert_w_kernel(WPack wp)
{
    __shared__ float tile[32][33];
    const int w = blockIdx.z;
    const int n0 = blockIdx.x * 32;
    const int k0 = blockIdx.y * 32;
    const float* __restrict__ W = wp.W[w];
    const int tx = threadIdx.x;   // 0..31
    const int ty = threadIdx.y;   // 0..7
#pragma unroll
    for (int i = 0; i < 4; i++) {
        int k = k0 + ty + i * 8;
        tile[ty + i * 8][tx] = W[(size_t)k * 1024 + n0 + tx];
    }
    __syncthreads();
#pragma unroll
    for (int i = 0; i < 4; i++) {
        int n = n0 + ty + i * 8;
        float v = tile[tx][ty + i * 8];
        __nv_bfloat16 hi = __float2bfloat16(v);
        __nv_bfloat16 lo = __float2bfloat16(v - __bfloat162float(hi));
        size_t off = (size_t)w * 1048576 + (size_t)n * 1024 + k0 + tx;
        g_wthi[off] = hi;
        g_wtlo[off] = lo;
    }
}

// ---------------------------------------------------------------------------
// HMMA projection GEMM: C[4096,6144] = X @ [6 weights] + bias
// 128x128x32 tile, 8 warps (2x4), 3x bf16-split, writes bf16 hi/lo head-major.
// ---------------------------------------------------------------------------
__global__ __launch_bounds__(256) void qkv_gemm_mma(WPack wp)
{
    __shared__ __nv_bfloat16 Ah[128][40], Al[128][40], Bh[128][40], Bl[128][40];

    const int tid = threadIdx.x;
    const int lane = tid & 31;
    const int wid = tid >> 5;
    const int wm = wid >> 2;        // 0..1  -> 64-row half
    const int wn = wid & 3;         // 0..3  -> 32-col quarter
    const int bn = blockIdx.x;      // 0..47
    const int bm = blockIdx.y;      // 0..31

    const __nv_bfloat16* __restrict__ ah = g_xhi + (size_t)(bm * 128) * 1024;
    const __nv_bfloat16* __restrict__ al = g_xlo + (size_t)(bm * 128) * 1024;
    const __nv_bfloat16* __restrict__ bhp = g_wthi + (size_t)(bn * 128) * 1024;
    const __nv_bfloat16* __restrict__ blp = g_wtlo + (size_t)(bn * 128) * 1024;

    float acc[4][4][4];
#pragma unroll
    for (int i = 0; i < 4; i++)
#pragma unroll
        for (int j = 0; j < 4; j++)
#pragma unroll
            for (int q = 0; q < 4; q++) acc[i][j][q] = 0.f;

    const int rsel = lane & 15;
    const int ksel = 8 * (lane >> 4);

    for (int kb = 0; kb < 32; kb++) {
        const int k0 = kb * 32;
        // stage gmem -> regs
        uint4 sa[2], sal[2], sb[2], sbl[2];
#pragma unroll
        for (int uu = 0; uu < 2; uu++) {
            int u = tid + uu * 256;             // 0..511
            int r = u >> 2, c = (u & 3) * 8;
            size_t go = (size_t)r * 1024 + k0 + c;
            sa[uu]  = *reinterpret_cast<const uint4*>(ah + go);
            sal[uu] = *reinterpret_cast<const uint4*>(al + go);
            sb[uu]  = *reinterpret_cast<const uint4*>(bhp + go);
            sbl[uu] = *reinterpret_cast<const uint4*>(blp + go);
        }
        __syncthreads();   // previous iteration's ldmatrix reads complete
#pragma unroll
        for (int uu = 0; uu < 2; uu++) {
            int u = tid + uu * 256;
            int r = u >> 2, c = (u & 3) * 8;
            *reinterpret_cast<uint4*>(&Ah[r][c]) = sa[uu];
            *reinterpret_cast<uint4*>(&Al[r][c]) = sal[uu];
            *reinterpret_cast<uint4*>(&Bh[r][c]) = sb[uu];
            *reinterpret_cast<uint4*>(&Bl[r][c]) = sbl[uu];
        }
        __syncthreads();

#pragma unroll
        for (int ks = 0; ks < 2; ks++) {
            const int kk = ks * 16 + ksel;
            uint32_t ahf[4][4], alf[4][4], bhf[4][2], blf[4][2];
#pragma unroll
            for (int mt = 0; mt < 4; mt++) {
                uint32_t adr = smem_u32(&Ah[wm * 64 + mt * 16 + rsel][kk]);
                LDSM_X4(ahf[mt][0], ahf[mt][1], ahf[mt][2], ahf[mt][3], adr);
                adr = smem_u32(&Al[wm * 64 + mt * 16 + rsel][kk]);
                LDSM_X4(alf[mt][0], alf[mt][1], alf[mt][2], alf[mt][3], adr);
            }
#pragma unroll
            for (int np = 0; np < 2; np++) {
                uint32_t r0, r1, r2, r3;
                uint32_t adr = smem_u32(&Bh[wn * 32 + np * 16 + rsel][kk]);
                LDSM_X4(r0, r1, r2, r3, adr);
                bhf[2 * np][0] = r0; bhf[2 * np][1] = r2;
                bhf[2 * np + 1][0] = r1; bhf[2 * np + 1][1] = r3;
                adr = smem_u32(&Bl[wn * 32 + np * 16 + rsel][kk]);
                LDSM_X4(r0, r1, r2, r3, adr);
                blf[2 * np][0] = r0; blf[2 * np][1] = r2;
                blf[2 * np + 1][0] = r1; blf[2 * np + 1][1] = r3;
            }
#pragma unroll
            for (int mt = 0; mt < 4; mt++)
#pragma unroll
                for (int nt = 0; nt < 4; nt++) {
                    MMA_BF16(acc[mt][nt], ahf[mt], bhf[nt][0], bhf[nt][1]);
                    MMA_BF16(acc[mt][nt], ahf[mt], blf[nt][0], blf[nt][1]);
                    MMA_BF16(acc[mt][nt], alf[mt], bhf[nt][0], bhf[nt][1]);
                }
        }
    }

    // Epilogue: bias + bf16 hi/lo split, scattered to head-major layout
#pragma unroll
    for (int mt = 0; mt < 4; mt++) {
        int m0 = bm * 128 + wm * 64 + mt * 16 + (lane >> 2);
#pragma unroll
        for (int half = 0; half < 2; half++) {
            int m = m0 + half * 8;
            int bb = m >> 10, s = m & 1023;
#pragma unroll
            for (int nt = 0; nt < 4; nt++) {
                int ng = bn * 128 + wn * 32 + nt * 8 + 2 * (lane & 3);
                int which = ng >> 10, rem = ng & 1023;
                int hh = rem >> 6, d = rem & 63;
                float2 bias2 = *reinterpret_cast<const float2*>(wp.b[which] + rem);
                float v0 = acc[mt][nt][half * 2 + 0] + bias2.x;
                float v1 = acc[mt][nt][half * 2 + 1] + bias2.y;
                __nv_bfloat16 h0 = __float2bfloat16(v0);
                __nv_bfloat16 h1 = __float2bfloat16(v1);
                float l0 = v0 - __bfloat162float(h0);
                float l1 = v1 - __bfloat162float(h1);
                size_t off = (((size_t)which * 4 + bb) * 16 + hh) * 65536 + (size_t)s * 64 + d;
                __nv_bfloat162 hp; hp.x = h0; hp.y = h1;
                *reinterpret_cast<uint32_t*>(&g_qkv_hi[off]) = *reinterpret_cast<uint32_t*>(&hp);
                *reinterpret_cast<uint32_t*>(&g_qkv_lo[off]) = pack_bf16x2(l0, l1);
            }
        }
    }
}

// ---------------------------------------------------------------------------
// HMMA flash attention. Block = 128 threads (4 warps), one block per
// (qtile 64 rows) x (b,h). Warp owns 16 q-rows. Online softmax in accum
// layout; P,V both hi/lo split. type=0 writes w0*ctx; type=1 accumulates.
// ---------------------------------------------------------------------------
__global__ __launch_bounds__(128) void attn_mma(const float* __restrict__ attn_w,
                                                float* __restrict__ out, int type)
{
    __shared__ __nv_bfloat16 Kh[64][72], Kl[64][72], Vh[64][72], Vl[64][72];

    const int tid = threadIdx.x;
    const int lane = tid & 31;
    const int warp = tid >> 5;
    const int qt = blockIdx.x;       // 0..15
    const int bhv = blockIdx.y;      // 0..63
    const int b = bhv >> 4, h = bhv & 15;

    const size_t base = ((size_t)b * 16 + h) * 65536;
    const __nv_bfloat16* __restrict__ qh = g_qkv_hi + (size_t)(type * 3 + 0) * 4194304 + base;
    const __nv_bfloat16* __restrict__ ql = g_qkv_lo + (size_t)(type * 3 + 0) * 4194304 + base;
    const __nv_bfloat16* __restrict__ kh = g_qkv_hi + (size_t)(type * 3 + 1) * 4194304 + base;
    const __nv_bfloat16* __restrict__ kl = g_qkv_lo + (size_t)(type * 3 + 1) * 4194304 + base;
    const __nv_bfloat16* __restrict__ vh = g_qkv_hi + (size_t)(type * 3 + 2) * 4194304 + base;
    const __nv_bfloat16* __restrict__ vl = g_qkv_lo + (size_t)(type * 3 + 2) * 4194304 + base;

    const int rsel = lane & 15;
    const int ksel = 8 * (lane >> 4);

    // ---- stage Q through K buffers, grab persistent Q fragments ----
#pragma unroll
    for (int uu = 0; uu < 4; uu++) {
        int u = tid + uu * 128;             // 0..511
        int r = u >> 3, c = (u & 7) * 8;
        size_t go = (size_t)(qt * 64 + r) * 64 + c;
        *reinterpret_cast<uint4*>(&Kh[r][c]) = *reinterpret_cast<const uint4*>(qh + go);
        *reinterpret_cast<uint4*>(&Kl[r][c]) = *reinterpret_cast<const uint4*>(ql + go);
    }
    __syncthreads();
    uint32_t qfh[4][4], qfl[4][4];
#pragma unroll
    for (int ks = 0; ks < 4; ks++) {
        int kk = ks * 16 + ksel;
        uint32_t adr = smem_u32(&Kh[warp * 16 + rsel][kk]);
        LDSM_X4(qfh[ks][0], qfh[ks][1], qfh[ks][2], qfh[ks][3], adr);
        adr = smem_u32(&Kl[warp * 16 + rsel][kk]);
        LDSM_X4(qfl[ks][0], qfl[ks][1], qfl[ks][2], qfl[ks][3], adr);
    }

    float o[8][4];
#pragma unroll
    for (int i = 0; i < 8; i++)
#pragma unroll
        for (int j = 0; j < 4; j++) o[i][j] = 0.f;
    float M0 = -1e30f, M1 = -1e30f, L0 = 0.f, L1 = 0.f;

    for (int kt = 0; kt < 16; kt++) {
        __syncthreads();    // all warps done with previous K/V (and Q staging)
#pragma unroll
        for (int uu = 0; uu < 4; uu++) {
            int u = tid + uu * 128;
            int r = u >> 3, c = (u & 7) * 8;
            size_t go = (size_t)(kt * 64 + r) * 64 + c;
            *reinterpret_cast<uint4*>(&Kh[r][c]) = *reinterpret_cast<const uint4*>(kh + go);
            *reinterpret_cast<uint4*>(&Kl[r][c]) = *reinterpret_cast<const uint4*>(kl + go);
            *reinterpret_cast<uint4*>(&Vh[r][c]) = *reinterpret_cast<const uint4*>(vh + go);
            *reinterpret_cast<uint4*>(&Vl[r][c]) = *reinterpret_cast<const uint4*>(vl + go);
        }
        __syncthreads();

        // ---- S = Q K^T (16 x 64), 3-way split ----
        float s[8][4];
#pragma unroll
        for (int i = 0; i < 8; i++)
#pragma unroll
            for (int j = 0; j < 4; j++) s[i][j] = 0.f;

#pragma unroll
        for (int ks = 0; ks < 4; ks++) {
            const int kk = ks * 16 + ksel;
            uint32_t bhf[8][2], blf[8][2];
#pragma unroll
            for (int np = 0; np < 4; np++) {
                uint32_t r0, r1, r2, r3;
                uint32_t adr = smem_u32(&Kh[np * 16 + rsel][kk]);
                LDSM_X4(r0, r1, r2, r3, adr);
                bhf[2 * np][0] = r0; bhf[2 * np][1] = r2;
                bhf[2 * np + 1][0] = r1; bhf[2 * np + 1][1] = r3;
                adr = smem_u32(&Kl[np * 16 + rsel][kk]);
                LDSM_X4(r0, r1, r2, r3, adr);
                blf[2 * np][0] = r0; blf[2 * np][1] = r2;
                blf[2 * np + 1][0] = r1; blf[2 * np + 1][1] = r3;
            }
#pragma unroll
            for (int nt = 0; nt < 8; nt++) {
                MMA_BF16(s[nt], qfh[ks], bhf[nt][0], bhf[nt][1]);
                MMA_BF16(s[nt], qfh[ks], blf[nt][0], blf[nt][1]);
                MMA_BF16(s[nt], qfl[ks], bhf[nt][0], bhf[nt][1]);
            }
        }

        // ---- online softmax (rows: lane/4 and lane/4+8; quad-lane reduce) ----
        float rm0 = -1e30f, rm1 = -1e30f;
#pragma unroll
        for (int nt = 0; nt < 8; nt++) {
#pragma unroll
            for (int j = 0; j < 4; j++) s[nt][j] *= 0.125f;
            rm0 = fmaxf(rm0, fmaxf(s[nt][0], s[nt][1]));
            rm1 = fmaxf(rm1, fmaxf(s[nt][2], s[nt][3]));
        }
        rm0 = fmaxf(rm0, __shfl_xor_sync(0xffffffffu, rm0, 1));
        rm0 = fmaxf(rm0, __shfl_xor_sync(0xffffffffu, rm0, 2));
        rm1 = fmaxf(rm1, __shfl_xor_sync(0xffffffffu, rm1, 1));
        rm1 = fmaxf(rm1, __shfl_xor_sync(0xffffffffu, rm1, 2));
        float mn0 = fmaxf(M0, rm0), mn1 = fmaxf(M1, rm1);
        float sc0 = __expf(M0 - mn0), sc1 = __expf(M1 - mn1);
        float rs0 = 0.f, rs1 = 0.f;
#pragma unroll
        for (int nt = 0; nt < 8; nt++) {
            s[nt][0] = __expf(s[nt][0] - mn0);
            s[nt][1] = __expf(s[nt][1] - mn0);
            s[nt][2] = __expf(s[nt][2] - mn1);
            s[nt][3] = __expf(s[nt][3] - mn1);
            rs0 += s[nt][0] + s[nt][1];
            rs1 += s[nt][2] + s[nt][3];
        }
        rs0 += __shfl_xor_sync(0xffffffffu, rs0, 1);
        rs0 += __shfl_xor_sync(0xffffffffu, rs0, 2);
        rs1 += __shfl_xor_sync(0xffffffffu, rs1, 1);
        rs1 += __shfl_xor_sync(0xffffffffu, rs1, 2);
        L0 = L0 * sc0 + rs0; M0 = mn0;
        L1 = L1 * sc1 + rs1; M1 = mn1;
#pragma unroll
        for (int dt = 0; dt < 8; dt++) {
            o[dt][0] *= sc0; o[dt][1] *= sc0;
            o[dt][2] *= sc1; o[dt][3] *= sc1;
        }

        // ---- pack P (hi/lo) into A fragments: accum->A register identity ----
        uint32_t ph[4][4], pl[4][4];
#pragma unroll
        for (int kp = 0; kp < 4; kp++) {
            const int t0 = 2 * kp, t1 = 2 * kp + 1;
            float p_[8] = {s[t0][0], s[t0][1], s[t0][2], s[t0][3],
                           s[t1][0], s[t1][1], s[t1][2], s[t1][3]};
            __nv_bfloat16 hb[8];
            float lb[8];
#pragma unroll
            for (int e = 0; e < 8; e++) {
                hb[e] = __float2bfloat16(p_[e]);
                lb[e] = p_[e] - __bfloat162float(hb[e]);
            }
            __nv_bfloat162 t;
            t.x = hb[0]; t.y = hb[1]; ph[kp][0] = *reinterpret_cast<uint32_t*>(&t);
            t.x = hb[2]; t.y = hb[3]; ph[kp][1] = *reinterpret_cast<uint32_t*>(&t);
            t.x = hb[4]; t.y = hb[5]; ph[kp][2] = *reinterpret_cast<uint32_t*>(&t);
            t.x = hb[6]; t.y = hb[7]; ph[kp][3] = *reinterpret_cast<uint32_t*>(&t);
            pl[kp][0] = pack_bf16x2(lb[0], lb[1]);
            pl[kp][1] = pack_bf16x2(lb[2], lb[3]);
            pl[kp][2] = pack_bf16x2(lb[4], lb[5]);
            pl[kp][3] = pack_bf16x2(lb[6], lb[7]);
        }

        // ---- O += P V  (V^T fragments via ldmatrix.trans) ----
        const int krow = ((lane >> 4) * 8) + (lane & 7);
        const int dcol = ((lane >> 3) & 1) * 8;
#pragma unroll
        for (int ks = 0; ks < 4; ks++) {
            uint32_t vhf[8][2], vlf[8][2];
#pragma unroll
            for (int dp = 0; dp < 4; dp++) {
                uint32_t r0, r1, r2, r3;
                uint32_t adr = smem_u32(&Vh[ks * 16 + krow][dp * 16 + dcol]);
                LDSM_X4_T(r0, r1, r2, r3, adr);
                vhf[2 * dp][0] = r0; vhf[2 * dp][1] = r2;
                vhf[2 * dp + 1][0] = r1; vhf[2 * dp + 1][1] = r3;
                adr = smem_u32(&Vl[ks * 16 + krow][dp * 16 + dcol]);
                LDSM_X4_T(r0, r1, r2, r3, adr);
                vlf[2 * dp][0] = r0; vlf[2 * dp][1] = r2;
                vlf[2 * dp + 1][0] = r1; vlf[2 * dp + 1][1] = r3;
            }
#pragma unroll
            for (int dt = 0; dt < 8; dt++) {
                MMA_BF16(o[dt], ph[ks], vhf[dt][0], vhf[dt][1]);
                MMA_BF16(o[dt], ph[ks], vlf[dt][0], vlf[dt][1]);
                MMA_BF16(o[dt], pl[ks], vhf[dt][0], vhf[dt][1]);
            }
        }
    }

    // ---- finalize: divide by L, apply stream weight, write/accumulate ----
    float w0a = attn_w[0], w1a = attn_w[1];
    float mx = fmaxf(w0a, w1a);
    float e0 = __expf(w0a - mx), e1 = __expf(w1a - mx);
    float wA = ((type == 0) ? e0 : e1) / (e0 + e1);
    float i0 = wA / L0, i1 = wA / L1;

    const int r0 = qt * 64 + warp * 16 + (lane >> 2);
#pragma unroll
    for (int dt = 0; dt < 8; dt++) {
        int col = h * 64 + dt * 8 + 2 * (lane & 3);
        float* p0 = out + ((size_t)b * 1024 + r0) * 1024 + col;
        float* p1 = out + ((size_t)b * 1024 + r0 + 8) * 1024 + col;
        if (type == 0) {
            p0[0] = o[dt][0] * i0; p0[1] = o[dt][1] * i0;
            p1[0] = o[dt][2] * i1; p1[1] = o[dt][3] * i1;
        } else {
            p0[0] += o[dt][0] * i0; p0[1] += o[dt][1] * i0;
            p1[0] += o[dt][2] * i1; p1[1] += o[dt][3] * i1;
        }
    }
}

// ---------------------------------------------------------------------------
// Launch
// ---------------------------------------------------------------------------
extern "C" void kernel_launch(void* const* d_in, const int* in_sizes, int n_in,
                              void* d_out, int out_size)
{
    (void)in_sizes; (void)n_in; (void)out_size;
    const float* x = (const float*)d_in[0];
    WPack wp;
    for (int i = 0; i < 6; i++) {
        wp.W[i] = (const float*)d_in[1 + 2 * i];
        wp.b[i] = (const float*)d_in[2 + 2 * i];
    }
    const float* attn_w = (const float*)d_in[13];
    float* out = (float*)d_out;

    // 1) bf16 hi/lo conversions
    convert_x_kernel<<<16384, 256>>>(x);
    convert_w_kernel<<<dim3(32, 32, 6), dim3(32, 8)>>>(wp);

    // 2) HMMA projection GEMM (writes bf16 hi/lo head-major scratch)
    qkv_gemm_mma<<<dim3(48, 32), 256>>>(wp);

    // 3) HMMA flash attention, two streams
    attn_mma<<<dim3(16, 64), 128>>>(attn_w, out, 0);
    attn_mma<<<dim3(16, 64), 128>>>(attn_w, out, 1);
}

// round 6
// speedup vs baseline: 2.8399x; 1.1662x over previous
#include <cuda_runtime.h>
#include <cuda_bf16.h>
#include <cstdint>
#include <math.h>

// Problem constants: B=4, S=1024, D=1024, H=16, DH=64
// head-major scratch: [which(6)][b(4)][h(16)][s(1024)][d(64)], bf16 hi/lo split
__device__ __nv_bfloat16 g_qkv_hi[6ull * 4 * 16 * 1024 * 64];
__device__ __nv_bfloat16 g_qkv_lo[6ull * 4 * 16 * 1024 * 64];
// bf16 split GEMM operands
__device__ __nv_bfloat16 g_xhi[4096ull * 1024];
__device__ __nv_bfloat16 g_xlo[4096ull * 1024];
// W transposed to [which][n][k] so B tiles are K-major
__device__ __nv_bfloat16 g_wthi[6ull * 1024 * 1024];
__device__ __nv_bfloat16 g_wtlo[6ull * 1024 * 1024];

struct WPack {
    const float* W[6];
    const float* b[6];
};

// ---------------------------------------------------------------------------
// mma / ldmatrix / cp.async helpers (sm_80+ portable; target is sm_100)
// ---------------------------------------------------------------------------
__device__ __forceinline__ uint32_t smem_u32(const void* p) {
    uint32_t a;
    asm("{ .reg .u64 t; cvta.to.shared.u64 t, %1; cvt.u32.u64 %0, t; }" : "=r"(a) : "l"(p));
    return a;
}

#define LDSM_X4(r0, r1, r2, r3, addr) \
    asm volatile("ldmatrix.sync.aligned.m8n8.x4.shared.b16 {%0,%1,%2,%3}, [%4];" \
                 : "=r"(r0), "=r"(r1), "=r"(r2), "=r"(r3) : "r"(addr))
#define LDSM_X4_T(r0, r1, r2, r3, addr) \
    asm volatile("ldmatrix.sync.aligned.m8n8.x4.trans.shared.b16 {%0,%1,%2,%3}, [%4];" \
                 : "=r"(r0), "=r"(r1), "=r"(r2), "=r"(r3) : "r"(addr))

#define MMA_BF16(d, a, b0_, b1_) \
    asm volatile("mma.sync.aligned.m16n8k16.row.col.f32.bf16.bf16.f32 " \
                 "{%0,%1,%2,%3}, {%4,%5,%6,%7}, {%8,%9}, {%0,%1,%2,%3};" \
                 : "+f"((d)[0]), "+f"((d)[1]), "+f"((d)[2]), "+f"((d)[3]) \
                 : "r"((a)[0]), "r"((a)[1]), "r"((a)[2]), "r"((a)[3]), "r"(b0_), "r"(b1_))

#define CP_ASYNC16(dst, src) \
    asm volatile("cp.async.cg.shared.global [%0], [%1], 16;" :: "r"(dst), "l"(src) : "memory")
#define CP_COMMIT() asm volatile("cp.async.commit_group;" ::: "memory")
#define CP_WAIT(N)  asm volatile("cp.async.wait_group %0;" :: "n"(N) : "memory")

__device__ __forceinline__ uint32_t pack_bf16x2(float a, float b) {
    __nv_bfloat162 t = __floats2bfloat162_rn(a, b);
    return *reinterpret_cast<uint32_t*>(&t);
}

// 64-col bf16 tile (128B rows), XOR-chunk swizzle. col must be a multiple of 8.
__device__ __forceinline__ uint32_t swz64(int r, int col) {
    return (uint32_t)((r << 7) + ((((col >> 3) ^ (r & 7)) << 4)));
}

// ---------------------------------------------------------------------------
// Convert X -> bf16 hi/lo (x4 vectorized)
// ---------------------------------------------------------------------------
__global__ __launch_bounds__(256) void convert_x_kernel(const float* __restrict__ x)
{
    int i = (blockIdx.x * 256 + threadIdx.x) * 4;
    float4 v = *reinterpret_cast<const float4*>(x + i);
    float f[4] = {v.x, v.y, v.z, v.w};
    __nv_bfloat16 h[4];
    float l[4];
#pragma unroll
    for (int e = 0; e < 4; e++) {
        h[e] = __float2bfloat16(f[e]);
        l[e] = f[e] - __bfloat162float(h[e]);
    }
    __nv_bfloat162 h01; h01.x = h[0]; h01.y = h[1];
    __nv_bfloat162 h23; h23.x = h[2]; h23.y = h[3];
    uint2 hw = make_uint2(*reinterpret_cast<uint32_t*>(&h01), *reinterpret_cast<uint32_t*>(&h23));
    uint2 lw = make_uint2(pack_bf16x2(l[0], l[1]), pack_bf16x2(l[2], l[3]));
    *reinterpret_cast<uint2*>(g_xhi + i) = hw;
    *reinterpret_cast<uint2*>(g_xlo + i) = lw;
}

// ---------------------------------------------------------------------------
// Convert + transpose W[k][n] -> Wt[n][k] bf16 hi/lo
// ---------------------------------------------------------------------------
__global__ __launch_bounds__(256) void convert_w_kernel(WPack wp)
{
    __shared__ float tile[32][33];
    const int w = blockIdx.z;
    const int n0 = blockIdx.x * 32;
    const int k0 = blockIdx.y * 32;
    const float* __restrict__ W = wp.W[w];
    const int tx = threadIdx.x;   // 0..31
    const int ty = threadIdx.y;   // 0..7
#pragma unroll
    for (int i = 0; i < 4; i++) {
        int k = k0 + ty + i * 8;
        tile[ty + i * 8][tx] = W[(size_t)k * 1024 + n0 + tx];
    }
    __syncthreads();
#pragma unroll
    for (int i = 0; i < 4; i++) {
        int n = n0 + ty + i * 8;
        float v = tile[tx][ty + i * 8];
        __nv_bfloat16 hi = __float2bfloat16(v);
        __nv_bfloat16 lo = __float2bfloat16(v - __bfloat162float(hi));
        size_t off = (size_t)w * 1048576 + (size_t)n * 1024 + k0 + tx;
        g_wthi[off] = hi;
        g_wtlo[off] = lo;
    }
}

// ---------------------------------------------------------------------------
// HMMA projection GEMM with 2-stage cp.async pipeline.
// C[4096,6144] = X @ [6 weights] + bias. 128x128x32 tile, 8 warps (2x4),
// 3x bf16-split, writes bf16 hi/lo head-major.
// Dynamic smem: 2 stages x {Ah,Al,Bh,Bl}[128][40] bf16 = 81920 B.
// ---------------------------------------------------------------------------
__global__ __launch_bounds__(256) void qkv_gemm_mma(WPack wp)
{
    extern __shared__ char dsm[];
    const uint32_t sb = smem_u32(dsm);

    const int tid = threadIdx.x;
    const int lane = tid & 31;
    const int wid = tid >> 5;
    const int wm = wid >> 2;        // 0..1  -> 64-row half
    const int wn = wid & 3;         // 0..3  -> 32-col quarter
    const int bn = blockIdx.x;      // 0..47
    const int bm = blockIdx.y;      // 0..31

    const __nv_bfloat16* __restrict__ ah = g_xhi + (size_t)(bm * 128) * 1024;
    const __nv_bfloat16* __restrict__ al = g_xlo + (size_t)(bm * 128) * 1024;
    const __nv_bfloat16* __restrict__ bhp = g_wthi + (size_t)(bn * 128) * 1024;
    const __nv_bfloat16* __restrict__ blp = g_wtlo + (size_t)(bn * 128) * 1024;

    // prefetch issue: per stage/array 128 rows x 4 chunks of 16B; 2 chunks/thread
    auto issue = [&](int kb, int st) {
        uint32_t stb = sb + st * 40960;
#pragma unroll
        for (int uu = 0; uu < 2; uu++) {
            int idx = tid + uu * 256;
            int r = idx >> 2, c = idx & 3;
            size_t go = (size_t)r * 1024 + kb * 32 + c * 8;
            uint32_t so = (uint32_t)(r * 80 + c * 16);
            CP_ASYNC16(stb + so,          ah + go);
            CP_ASYNC16(stb + 10240 + so,  al + go);
            CP_ASYNC16(stb + 20480 + so,  bhp + go);
            CP_ASYNC16(stb + 30720 + so,  blp + go);
        }
    };

    float acc[4][4][4];
#pragma unroll
    for (int i = 0; i < 4; i++)
#pragma unroll
        for (int j = 0; j < 4; j++)
#pragma unroll
            for (int q = 0; q < 4; q++) acc[i][j][q] = 0.f;

    const int rsel = lane & 15;
    const int ksel = 8 * (lane >> 4);

    issue(0, 0); CP_COMMIT();
    issue(1, 1); CP_COMMIT();

    for (int kb = 0; kb < 32; kb++) {
        const int st = kb & 1;
        if (kb < 30) { CP_WAIT(1); } else { CP_WAIT(0); }
        __syncthreads();

        const uint32_t stb = sb + st * 40960;
#pragma unroll
        for (int ks = 0; ks < 2; ks++) {
            const uint32_t kk2 = (uint32_t)((ks * 16 + ksel) * 2);   // byte offset in row
            uint32_t ahf[4][4], alf[4][4], bhf[4][2], blf[4][2];
#pragma unroll
            for (int mt = 0; mt < 4; mt++) {
                uint32_t adr = stb + (uint32_t)((wm * 64 + mt * 16 + rsel) * 80) + kk2;
                LDSM_X4(ahf[mt][0], ahf[mt][1], ahf[mt][2], ahf[mt][3], adr);
                LDSM_X4(alf[mt][0], alf[mt][1], alf[mt][2], alf[mt][3], adr + 10240);
            }
#pragma unroll
            for (int np = 0; np < 2; np++) {
                uint32_t r0, r1, r2, r3;
                uint32_t adr = stb + 20480 + (uint32_t)((wn * 32 + np * 16 + rsel) * 80) + kk2;
                LDSM_X4(r0, r1, r2, r3, adr);
                bhf[2 * np][0] = r0; bhf[2 * np][1] = r2;
                bhf[2 * np + 1][0] = r1; bhf[2 * np + 1][1] = r3;
                LDSM_X4(r0, r1, r2, r3, adr + 10240);
                blf[2 * np][0] = r0; blf[2 * np][1] = r2;
                blf[2 * np + 1][0] = r1; blf[2 * np + 1][1] = r3;
            }
#pragma unroll
            for (int mt = 0; mt < 4; mt++)
#pragma unroll
                for (int nt = 0; nt < 4; nt++) {
                    MMA_BF16(acc[mt][nt], ahf[mt], bhf[nt][0], bhf[nt][1]);
                    MMA_BF16(acc[mt][nt], ahf[mt], blf[nt][0], blf[nt][1]);
                    MMA_BF16(acc[mt][nt], alf[mt], bhf[nt][0], bhf[nt][1]);
                }
        }
        __syncthreads();
        if (kb + 2 < 32) { issue(kb + 2, st); CP_COMMIT(); }
    }

    // Epilogue: bias + bf16 hi/lo split, scattered to head-major layout
#pragma unroll
    for (int mt = 0; mt < 4; mt++) {
        int m0 = bm * 128 + wm * 64 + mt * 16 + (lane >> 2);
#pragma unroll
        for (int half = 0; half < 2; half++) {
            int m = m0 + half * 8;
            int bb = m >> 10, s = m & 1023;
#pragma unroll
            for (int nt = 0; nt < 4; nt++) {
                int ng = bn * 128 + wn * 32 + nt * 8 + 2 * (lane & 3);
                int which = ng >> 10, rem = ng & 1023;
                int hh = rem >> 6, d = rem & 63;
                float2 bias2 = *reinterpret_cast<const float2*>(wp.b[which] + rem);
                float v0 = acc[mt][nt][half * 2 + 0] + bias2.x;
                float v1 = acc[mt][nt][half * 2 + 1] + bias2.y;
                __nv_bfloat16 h0 = __float2bfloat16(v0);
                __nv_bfloat16 h1 = __float2bfloat16(v1);
                float l0 = v0 - __bfloat162float(h0);
                float l1 = v1 - __bfloat162float(h1);
                size_t off = (((size_t)which * 4 + bb) * 16 + hh) * 65536 + (size_t)s * 64 + d;
                __nv_bfloat162 hp; hp.x = h0; hp.y = h1;
                *reinterpret_cast<uint32_t*>(&g_qkv_hi[off]) = *reinterpret_cast<uint32_t*>(&hp);
                *reinterpret_cast<uint32_t*>(&g_qkv_lo[off]) = pack_bf16x2(l0, l1);
            }
        }
    }
}

// ---------------------------------------------------------------------------
// HMMA flash attention with 2-stage cp.async K/V pipeline.
// Block = 128 threads (4 warps), one block per (qtile 64 rows) x (b,h).
// Dynamic smem: 2 stages x {Kh,Kl,Vh,Vl} 64x64 bf16 swizzled = 65536 B.
// type=0 writes w0*ctx; type=1 (second launch) accumulates w1*sctx.
// ---------------------------------------------------------------------------
__global__ __launch_bounds__(128) void attn_mma(const float* __restrict__ attn_w,
                                                float* __restrict__ out, int type)
{
    extern __shared__ char dsm[];
    const uint32_t sb = smem_u32(dsm);

    const int tid = threadIdx.x;
    const int lane = tid & 31;
    const int warp = tid >> 5;
    const int qt = blockIdx.x;       // 0..15
    const int bhv = blockIdx.y;      // 0..63
    const int b = bhv >> 4, h = bhv & 15;

    const size_t base = ((size_t)b * 16 + h) * 65536;
    const __nv_bfloat16* __restrict__ qh = g_qkv_hi + (size_t)(type * 3 + 0) * 4194304 + base;
    const __nv_bfloat16* __restrict__ ql = g_qkv_lo + (size_t)(type * 3 + 0) * 4194304 + base;
    const __nv_bfloat16* __restrict__ kh = g_qkv_hi + (size_t)(type * 3 + 1) * 4194304 + base;
    const __nv_bfloat16* __restrict__ kl = g_qkv_lo + (size_t)(type * 3 + 1) * 4194304 + base;
    const __nv_bfloat16* __restrict__ vh = g_qkv_hi + (size_t)(type * 3 + 2) * 4194304 + base;
    const __nv_bfloat16* __restrict__ vl = g_qkv_lo + (size_t)(type * 3 + 2) * 4194304 + base;

    const int rsel = lane & 15;
    const int ksel = 8 * (lane >> 4);

    // ---- stage Q through stage-0 K buffers via cp.async, grab Q fragments ----
#pragma unroll
    for (int u = 0; u < 4; u++) {
        int idx = tid + u * 128;            // 0..511
        int r = idx >> 3, c = idx & 7;
        size_t go = (size_t)(qt * 64 + r) * 64 + c * 8;
        uint32_t so = swz64(r, c * 8);
        CP_ASYNC16(sb + so,        qh + go);
        CP_ASYNC16(sb + 8192 + so, ql + go);
    }
    CP_COMMIT();
    CP_WAIT(0);
    __syncthreads();

    uint32_t qfh[4][4], qfl[4][4];
#pragma unroll
    for (int ks = 0; ks < 4; ks++) {
        int kk = ks * 16 + ksel;
        uint32_t adr = sb + swz64(warp * 16 + rsel, kk);
        LDSM_X4(qfh[ks][0], qfh[ks][1], qfh[ks][2], qfh[ks][3], adr);
        LDSM_X4(qfl[ks][0], qfl[ks][1], qfl[ks][2], qfl[ks][3], adr + 8192);
    }
    __syncthreads();   // all warps done reading stage 0 before K/V prefetch

    // K/V prefetch: per stage/array 64 rows x 8 chunks; 4 chunks/thread
    auto issue_kv = [&](int kt, int st) {
        uint32_t stb = sb + st * 32768;
#pragma unroll
        for (int u = 0; u < 4; u++) {
            int idx = tid + u * 128;
            int r = idx >> 3, c = idx & 7;
            size_t go = (size_t)(kt * 64 + r) * 64 + c * 8;
            uint32_t so = swz64(r, c * 8);
            CP_ASYNC16(stb + so,         kh + go);
            CP_ASYNC16(stb + 8192 + so,  kl + go);
            CP_ASYNC16(stb + 16384 + so, vh + go);
            CP_ASYNC16(stb + 24576 + so, vl + go);
        }
    };

    issue_kv(0, 0); CP_COMMIT();
    issue_kv(1, 1); CP_COMMIT();

    float o[8][4];
#pragma unroll
    for (int i = 0; i < 8; i++)
#pragma unroll
        for (int j = 0; j < 4; j++) o[i][j] = 0.f;
    float M0 = -1e30f, M1 = -1e30f, L0 = 0.f, L1 = 0.f;

    for (int kt = 0; kt < 16; kt++) {
        const int st = kt & 1;
        if (kt < 14) { CP_WAIT(1); } else { CP_WAIT(0); }
        __syncthreads();
        const uint32_t stb = sb + st * 32768;

        // ---- S = Q K^T (16 x 64), 3-way split ----
        float s[8][4];
#pragma unroll
        for (int i = 0; i < 8; i++)
#pragma unroll
            for (int j = 0; j < 4; j++) s[i][j] = 0.f;

#pragma unroll
        for (int ks = 0; ks < 4; ks++) {
            const int kk = ks * 16 + ksel;
            uint32_t bhf[8][2], blf[8][2];
#pragma unroll
            for (int np = 0; np < 4; np++) {
                uint32_t r0, r1, r2, r3;
                uint32_t adr = stb + swz64(np * 16 + rsel, kk);
                LDSM_X4(r0, r1, r2, r3, adr);
                bhf[2 * np][0] = r0; bhf[2 * np][1] = r2;
                bhf[2 * np + 1][0] = r1; bhf[2 * np + 1][1] = r3;
                LDSM_X4(r0, r1, r2, r3, adr + 8192);
                blf[2 * np][0] = r0; blf[2 * np][1] = r2;
                blf[2 * np + 1][0] = r1; blf[2 * np + 1][1] = r3;
            }
#pragma unroll
            for (int nt = 0; nt < 8; nt++) {
                MMA_BF16(s[nt], qfh[ks], bhf[nt][0], bhf[nt][1]);
                MMA_BF16(s[nt], qfh[ks], blf[nt][0], blf[nt][1]);
                MMA_BF16(s[nt], qfl[ks], bhf[nt][0], bhf[nt][1]);
            }
        }

        // ---- online softmax (rows: lane/4 and lane/4+8; quad-lane reduce) ----
        float rm0 = -1e30f, rm1 = -1e30f;
#pragma unroll
        for (int nt = 0; nt < 8; nt++) {
#pragma unroll
            for (int j = 0; j < 4; j++) s[nt][j] *= 0.125f;
            rm0 = fmaxf(rm0, fmaxf(s[nt][0], s[nt][1]));
            rm1 = fmaxf(rm1, fmaxf(s[nt][2], s[nt][3]));
        }
        rm0 = fmaxf(rm0, __shfl_xor_sync(0xffffffffu, rm0, 1));
        rm0 = fmaxf(rm0, __shfl_xor_sync(0xffffffffu, rm0, 2));
        rm1 = fmaxf(rm1, __shfl_xor_sync(0xffffffffu, rm1, 1));
        rm1 = fmaxf(rm1, __shfl_xor_sync(0xffffffffu, rm1, 2));
        float mn0 = fmaxf(M0, rm0), mn1 = fmaxf(M1, rm1);
        float sc0 = __expf(M0 - mn0), sc1 = __expf(M1 - mn1);
        float rs0 = 0.f, rs1 = 0.f;
#pragma unroll
        for (int nt = 0; nt < 8; nt++) {
            s[nt][0] = __expf(s[nt][0] - mn0);
            s[nt][1] = __expf(s[nt][1] - mn0);
            s[nt][2] = __expf(s[nt][2] - mn1);
            s[nt][3] = __expf(s[nt][3] - mn1);
            rs0 += s[nt][0] + s[nt][1];
            rs1 += s[nt][2] + s[nt][3];
        }
        rs0 += __shfl_xor_sync(0xffffffffu, rs0, 1);
        rs0 += __shfl_xor_sync(0xffffffffu, rs0, 2);
        rs1 += __shfl_xor_sync(0xffffffffu, rs1, 1);
        rs1 += __shfl_xor_sync(0xffffffffu, rs1, 2);
        L0 = L0 * sc0 + rs0; M0 = mn0;
        L1 = L1 * sc1 + rs1; M1 = mn1;
#pragma unroll
        for (int dt = 0; dt < 8; dt++) {
            o[dt][0] *= sc0; o[dt][1] *= sc0;
            o[dt][2] *= sc1; o[dt][3] *= sc1;
        }

        // ---- pack P (hi/lo) into A fragments: accum->A register identity ----
        uint32_t ph[4][4], pl[4][4];
#pragma unroll
        for (int kp = 0; kp < 4; kp++) {
            const int t0 = 2 * kp, t1 = 2 * kp + 1;
            float p_[8] = {s[t0][0], s[t0][1], s[t0][2], s[t0][3],
                           s[t1][0], s[t1][1], s[t1][2], s[t1][3]};
            __nv_bfloat16 hb[8];
            float lb[8];
#pragma unroll
            for (int e = 0; e < 8; e++) {
                hb[e] = __float2bfloat16(p_[e]);
                lb[e] = p_[e] - __bfloat162float(hb[e]);
            }
            __nv_bfloat162 t;
            t.x = hb[0]; t.y = hb[1]; ph[kp][0] = *reinterpret_cast<uint32_t*>(&t);
            t.x = hb[2]; t.y = hb[3]; ph[kp][1] = *reinterpret_cast<uint32_t*>(&t);
            t.x = hb[4]; t.y = hb[5]; ph[kp][2] = *reinterpret_cast<uint32_t*>(&t);
            t.x = hb[6]; t.y = hb[7]; ph[kp][3] = *reinterpret_cast<uint32_t*>(&t);
            pl[kp][0] = pack_bf16x2(lb[0], lb[1]);
            pl[kp][1] = pack_bf16x2(lb[2], lb[3]);
            pl[kp][2] = pack_bf16x2(lb[4], lb[5]);
            pl[kp][3] = pack_bf16x2(lb[6], lb[7]);
        }

        // ---- O += P V  (V^T fragments via ldmatrix.trans) ----
        const int krow = ((lane >> 4) * 8) + (lane & 7);
        const int dcol = ((lane >> 3) & 1) * 8;
#pragma unroll
        for (int ks = 0; ks < 4; ks++) {
            uint32_t vhf[8][2], vlf[8][2];
#pragma unroll
            for (int dp = 0; dp < 4; dp++) {
                uint32_t r0, r1, r2, r3;
                uint32_t adr = stb + 16384 + swz64(ks * 16 + krow, dp * 16 + dcol);
                LDSM_X4_T(r0, r1, r2, r3, adr);
                vhf[2 * dp][0] = r0; vhf[2 * dp][1] = r2;
                vhf[2 * dp + 1][0] = r1; vhf[2 * dp + 1][1] = r3;
                LDSM_X4_T(r0, r1, r2, r3, adr + 8192);
                vlf[2 * dp][0] = r0; vlf[2 * dp][1] = r2;
                vlf[2 * dp + 1][0] = r1; vlf[2 * dp + 1][1] = r3;
            }
#pragma unroll
            for (int dt = 0; dt < 8; dt++) {
                MMA_BF16(o[dt], ph[ks], vhf[dt][0], vhf[dt][1]);
                MMA_BF16(o[dt], ph[ks], vlf[dt][0], vlf[dt][1]);
                MMA_BF16(o[dt], pl[ks], vhf[dt][0], vhf[dt][1]);
            }
        }
        __syncthreads();
        if (kt + 2 < 16) { issue_kv(kt + 2, st); CP_COMMIT(); }
    }

    // ---- finalize: divide by L, apply stream weight, write/accumulate ----
    float w0a = attn_w[0], w1a = attn_w[1];
    float mx = fmaxf(w0a, w1a);
    float e0 = __expf(w0a - mx), e1 = __expf(w1a - mx);
    float wA = ((type == 0) ? e0 : e1) / (e0 + e1);
    float i0 = wA / L0, i1 = wA / L1;

    const int r0 = qt * 64 + warp * 16 + (lane >> 2);
#pragma unroll
    for (int dt = 0; dt < 8; dt++) {
        int col = h * 64 + dt * 8 + 2 * (lane & 3);
        float* p0 = out + ((size_t)b * 1024 + r0) * 1024 + col;
        float* p1 = out + ((size_t)b * 1024 + r0 + 8) * 1024 + col;
        if (type == 0) {
            p0[0] = o[dt][0] * i0; p0[1] = o[dt][1] * i0;
            p1[0] = o[dt][2] * i1; p1[1] = o[dt][3] * i1;
        } else {
            p0[0] += o[dt][0] * i0; p0[1] += o[dt][1] * i0;
            p1[0] += o[dt][2] * i1; p1[1] += o[dt][3] * i1;
        }
    }
}

// ---------------------------------------------------------------------------
// Launch
// ---------------------------------------------------------------------------
extern "C" void kernel_launch(void* const* d_in, const int* in_sizes, int n_in,
                              void* d_out, int out_size)
{
    (void)in_sizes; (void)n_in; (void)out_size;
    const float* x = (const float*)d_in[0];
    WPack wp;
    for (int i = 0; i < 6; i++) {
        wp.W[i] = (const float*)d_in[1 + 2 * i];
        wp.b[i] = (const float*)d_in[2 + 2 * i];
    }
    const float* attn_w = (const float*)d_in[13];
    float* out = (float*)d_out;

    const int GEMM_SMEM = 81920;   // 2 stages x 4 arrays x 128x40 bf16
    const int ATTN_SMEM = 65536;   // 2 stages x 4 arrays x 64x64 bf16 (swizzled)
    cudaFuncSetAttribute(qkv_gemm_mma, cudaFuncAttributeMaxDynamicSharedMemorySize, GEMM_SMEM);
    cudaFuncSetAttribute(attn_mma, cudaFuncAttributeMaxDynamicSharedMemorySize, ATTN_SMEM);

    // 1) bf16 hi/lo conversions
    convert_x_kernel<<<4096, 256>>>(x);
    convert_w_kernel<<<dim3(32, 32, 6), dim3(32, 8)>>>(wp);

    // 2) HMMA projection GEMM (cp.async pipelined)
    qkv_gemm_mma<<<dim3(48, 32), 256, GEMM_SMEM>>>(wp);

    // 3) HMMA flash attention, two streams (cp.async pipelined)
    attn_mma<<<dim3(16, 64), 128, ATTN_SMEM>>>(attn_w, out, 0);
    attn_mma<<<dim3(16, 64), 128, ATTN_SMEM>>>(attn_w, out, 1);
}